// round 6
// baseline (speedup 1.0000x reference)
#include <cuda_runtime.h>
#include <cuda_fp16.h>
#include <cstdint>

// ============================================================================
// GraphRec UV_Aggregator — mma.sync m16n8k16 fp16 fused kernel, 2 CTAs/SM.
// compute_103-safe. 296 persistent CTAs x 256 threads (~107KB smem each).
// R6: vectorized smem hotspots (STS.128 gather, STS.64 epilogues, LDS.128
// uvatt) — same math as R5, fewer L1 wavefronts.
// ============================================================================

#define TPB   256
#define NB    2
#define LHIST 50
#define VROWS 100
#define SA    136    // halves stride, 128-k buffers
#define SH    72     // halves stride, 64-k buffers

// ---- smem byte offsets ----
#define O_A0   0u        // 128 x SA halves : X, later o in cols 0..63
#define O_H    34816u    // 128 x SH halves : hidden / H2
#define O_W1   53248u    // 64 x SA halves
#define O_A1W  70656u    // 64 x SA halves (A1_top k 0..63, A1_bot k 64..127)
#define O_W2   88064u    // 64 x SH halves
#define O_A2W  97280u
#define O_B1   106496u
#define O_B2   106752u
#define O_AB1  107008u
#define O_AB2  107264u
#define O_A3   107520u
#define O_UV   107776u   // 2 x 64 fp32
#define O_UVA  108288u   // 2 x 64 fp32 : uv @ A1_bot
#define O_LGP  108800u   // 2 x 128 fp32 logit partials
#define SMEM_BYTES 109824u

__device__ __forceinline__ void mma16(float (&d)[4], uint32_t a0, uint32_t a1,
                                      uint32_t a2, uint32_t a3, uint32_t b0, uint32_t b1) {
    asm volatile(
        "mma.sync.aligned.m16n8k16.row.col.f32.f16.f16.f32 "
        "{%0,%1,%2,%3}, {%4,%5,%6,%7}, {%8,%9}, {%0,%1,%2,%3};"
        : "+f"(d[0]), "+f"(d[1]), "+f"(d[2]), "+f"(d[3])
        : "r"(a0), "r"(a1), "r"(a2), "r"(a3), "r"(b0), "r"(b1));
}

__device__ __forceinline__ uint32_t h2(float lo, float hi) {
    __half2 h = __floats2half2_rn(lo, hi);
    return *reinterpret_cast<uint32_t*>(&h);
}

// fp16 storage index of logical col c within a row (pair-permuted k16 groups)
__device__ __forceinline__ int offcol(int c) {
    int gg = c >> 4, kr = c & 15, p = kr >> 1;
    int slot = (p & 3) * 2 + (p >> 2);
    return gg * 16 + slot * 2 + (kr & 1);
}

// GEMM: C[2 m16][4 n8] += A(rows 32wq..+31) @ B(cols 32wh..+31)^T
template <int KST, int SAs, int SBs>
__device__ __forceinline__ void gemm(const __half* __restrict__ As,
                                     const __half* __restrict__ Bs,
                                     float (&d)[2][4][4],
                                     int wq, int wh, int r, int m) {
    const __half* pa = As + (wq * 32 + r) * SAs + m * 4;
    const __half* pb = Bs + (wh * 32 + r) * SBs + m * 4;
#pragma unroll
    for (int g = 0; g < KST; g++) {
        uint2 aA = *(const uint2*)(pa + 16 * g);
        uint2 aB = *(const uint2*)(pa + 8 * SAs + 16 * g);
        uint2 aC = *(const uint2*)(pa + 16 * SAs + 16 * g);
        uint2 aD = *(const uint2*)(pa + 24 * SAs + 16 * g);
        uint2 b0 = *(const uint2*)(pb + 16 * g);
        uint2 b1 = *(const uint2*)(pb + 8 * SBs + 16 * g);
        uint2 b2 = *(const uint2*)(pb + 16 * SBs + 16 * g);
        uint2 b3 = *(const uint2*)(pb + 24 * SBs + 16 * g);
        mma16(d[0][0], aA.x, aB.x, aA.y, aB.y, b0.x, b0.y);
        mma16(d[0][1], aA.x, aB.x, aA.y, aB.y, b1.x, b1.y);
        mma16(d[0][2], aA.x, aB.x, aA.y, aB.y, b2.x, b2.y);
        mma16(d[0][3], aA.x, aB.x, aA.y, aB.y, b3.x, b3.y);
        mma16(d[1][0], aC.x, aD.x, aC.y, aD.y, b0.x, b0.y);
        mma16(d[1][1], aC.x, aD.x, aC.y, aD.y, b1.x, b1.y);
        mma16(d[1][2], aC.x, aD.x, aC.y, aD.y, b2.x, b2.y);
        mma16(d[1][3], aC.x, aD.x, aC.y, aD.y, b3.x, b3.y);
    }
}

__device__ __forceinline__ void zero_acc(float (&d)[2][4][4]) {
#pragma unroll
    for (int i = 0; i < 2; i++)
#pragma unroll
        for (int j = 0; j < 4; j++)
#pragma unroll
            for (int k = 0; k < 4; k++) d[i][j][k] = 0.f;
}

// relu(d + bias) -> half k-storage, STS.64 (nt-pairs merged)
template <int SD>
__device__ __forceinline__ void epi_store(float (&d)[2][4][4], const float* __restrict__ bias,
                                          __half* __restrict__ dst,
                                          int wq, int wh, int r, int m) {
#pragma unroll
    for (int mt = 0; mt < 2; mt++) {
        int row0 = wq * 32 + mt * 16 + r;
#pragma unroll
        for (int np = 0; np < 2; np++) {
            int ca = wh * 32 + np * 16 + 2 * m;   // nt = 2np
            int cb = ca + 8;                      // nt = 2np+1
            float ba0 = bias[ca], ba1 = bias[ca + 1];
            float bb0 = bias[cb], bb1 = bias[cb + 1];
            int hoff = (wh * 2 + np) * 16 + m * 4;
            uint2 v0, v1;
            v0.x = h2(fmaxf(d[mt][2*np][0] + ba0, 0.f), fmaxf(d[mt][2*np][1] + ba1, 0.f));
            v0.y = h2(fmaxf(d[mt][2*np+1][0] + bb0, 0.f), fmaxf(d[mt][2*np+1][1] + bb1, 0.f));
            v1.x = h2(fmaxf(d[mt][2*np][2] + ba0, 0.f), fmaxf(d[mt][2*np][3] + ba1, 0.f));
            v1.y = h2(fmaxf(d[mt][2*np+1][2] + bb0, 0.f), fmaxf(d[mt][2*np+1][3] + bb1, 0.f));
            *reinterpret_cast<uint2*>(dst + row0 * SD + hoff) = v0;
            *reinterpret_cast<uint2*>(dst + (row0 + 8) * SD + hoff) = v1;
        }
    }
}

// epi3: relu(d + ab1 + uvatt[node(row)]) -> half k-storage, STS.64
__device__ __forceinline__ void epi3(float (&d)[2][4][4], const float* __restrict__ bias,
                                     const float* __restrict__ uva,
                                     __half* __restrict__ dst,
                                     int wq, int wh, int r, int m) {
#pragma unroll
    for (int mt = 0; mt < 2; mt++) {
        int row0 = wq * 32 + mt * 16 + r;
        int na = (row0 >= LHIST) ? 1 : 0;
        int nb = (row0 + 8 >= LHIST) ? 1 : 0;
#pragma unroll
        for (int np = 0; np < 2; np++) {
            int ca = wh * 32 + np * 16 + 2 * m;
            int cb = ca + 8;
            float ba0 = bias[ca] , ba1 = bias[ca + 1];
            float bb0 = bias[cb] , bb1 = bias[cb + 1];
            float uaa0 = uva[na * 64 + ca], uaa1 = uva[na * 64 + ca + 1];
            float uab0 = uva[na * 64 + cb], uab1 = uva[na * 64 + cb + 1];
            float uba0 = uva[nb * 64 + ca], uba1 = uva[nb * 64 + ca + 1];
            float ubb0 = uva[nb * 64 + cb], ubb1 = uva[nb * 64 + cb + 1];
            int hoff = (wh * 2 + np) * 16 + m * 4;
            uint2 v0, v1;
            v0.x = h2(fmaxf(d[mt][2*np][0] + ba0 + uaa0, 0.f),
                      fmaxf(d[mt][2*np][1] + ba1 + uaa1, 0.f));
            v0.y = h2(fmaxf(d[mt][2*np+1][0] + bb0 + uab0, 0.f),
                      fmaxf(d[mt][2*np+1][1] + bb1 + uab1, 0.f));
            v1.x = h2(fmaxf(d[mt][2*np][2] + ba0 + uba0, 0.f),
                      fmaxf(d[mt][2*np][3] + ba1 + uba1, 0.f));
            v1.y = h2(fmaxf(d[mt][2*np+1][2] + bb0 + ubb0, 0.f),
                      fmaxf(d[mt][2*np+1][3] + bb1 + ubb1, 0.f));
            *reinterpret_cast<uint2*>(dst + row0 * SH + hoff) = v0;
            *reinterpret_cast<uint2*>(dst + (row0 + 8) * SH + hoff) = v1;
        }
    }
}

// stage weight W[K][64] (gmem row-major) -> half dst[n][k-storage].
__device__ __forceinline__ void stage_wh(__half* __restrict__ dst, const float* __restrict__ W,
                                         int K, int strh, int tid) {
    for (int idx = tid; idx < K * 64; idx += TPB) {
        int k = idx >> 6, n = idx & 63;
        dst[n * strh + offcol(k)] = __float2half_rn(W[idx]);
    }
}

// pack 16 floats of one k16-group into 2 uint4s (pair-permuted slot order)
__device__ __forceinline__ void pack16(const float4& f0, const float4& f1,
                                       const float4& f2, const float4& f3,
                                       uint4& lo, uint4& hi) {
    lo.x = h2(f0.x, f0.y);  // cols 0,1
    lo.y = h2(f2.x, f2.y);  // cols 8,9
    lo.z = h2(f0.z, f0.w);  // cols 2,3
    lo.w = h2(f2.z, f2.w);  // cols 10,11
    hi.x = h2(f1.x, f1.y);  // cols 4,5
    hi.y = h2(f3.x, f3.y);  // cols 12,13
    hi.z = h2(f1.z, f1.w);  // cols 6,7
    hi.w = h2(f3.z, f3.w);  // cols 14,15
}

__global__ __launch_bounds__(TPB, 2)
void uv_agg_h3(const int* __restrict__ nodes,
               const int* __restrict__ hist_uv,
               const int* __restrict__ hist_r,
               const float* __restrict__ v2e,
               const float* __restrict__ u2e,
               const float* __restrict__ r2e,
               const float* __restrict__ w1, const float* __restrict__ b1,
               const float* __restrict__ w2, const float* __restrict__ b2,
               const float* __restrict__ a1w, const float* __restrict__ a1b,
               const float* __restrict__ a2w, const float* __restrict__ a2b,
               const float* __restrict__ a3w, const float* __restrict__ a3b,
               float* __restrict__ out, int ngroups) {
    extern __shared__ char smem[];
    __half* hA0  = reinterpret_cast<__half*>(smem + O_A0);
    __half* hH   = reinterpret_cast<__half*>(smem + O_H);
    __half* hW1  = reinterpret_cast<__half*>(smem + O_W1);
    __half* hA1W = reinterpret_cast<__half*>(smem + O_A1W);
    __half* hW2  = reinterpret_cast<__half*>(smem + O_W2);
    __half* hA2W = reinterpret_cast<__half*>(smem + O_A2W);
    float* fB1  = reinterpret_cast<float*>(smem + O_B1);
    float* fB2  = reinterpret_cast<float*>(smem + O_B2);
    float* fAB1 = reinterpret_cast<float*>(smem + O_AB1);
    float* fAB2 = reinterpret_cast<float*>(smem + O_AB2);
    float* fA3  = reinterpret_cast<float*>(smem + O_A3);
    float* fUV  = reinterpret_cast<float*>(smem + O_UV);
    float* fUVA = reinterpret_cast<float*>(smem + O_UVA);
    float* fLGP = reinterpret_cast<float*>(smem + O_LGP);

    const int tid = threadIdx.x;
    const int wid = tid >> 5, lane = tid & 31;
    const int wq = wid & 3;      // row octant (32 rows of 128)
    const int wh = wid >> 2;     // col half (32 cols of 64)
    const int r = lane >> 2, m = lane & 3;

    // ---- stage weights + biases once per CTA ----
    stage_wh(hW1, w1, 128, SA, tid);
    stage_wh(hA1W, a1w, 128, SA, tid);
    stage_wh(hW2, w2, 64, SH, tid);
    stage_wh(hA2W, a2w, 64, SH, tid);
    if (tid < 64) {
        fB1[tid]  = b1[tid];
        fB2[tid]  = b2[tid];
        fAB1[tid] = a1b[tid];
        fAB2[tid] = a2b[tid];
        fA3[tid]  = a3w[tid];
    }
    __syncthreads();

    const int gr = tid >> 1, ghalf = tid & 1;   // gather: row 0..127, col-half
    const bool gvalid = gr < VROWS;
    const int gn = (gr >= LHIST) ? 1 : 0;
    const int gl = gr - gn * LHIST;

    const int sn = tid >> 6;            // softmax: node (tid<128)
    const int sd = tid & 63;            // softmax: dim
    const int sdo = offcol(sd);

    for (int g = blockIdx.x; g < ngroups; g += gridDim.x) {
        const int b0 = g * NB;

        // ---- gather uv_rep + X = [e_uv|e_r] -> A0 (STS.128) ----
        if (tid < 128) {
            int n = tid >> 6, d2 = tid & 63;
            fUV[n * 64 + d2] = u2e[(size_t)nodes[b0 + n] * 64 + d2];
        }
        if (gvalid) {
            int hidx = (b0 + gn) * LHIST + gl;
            const float* src = ghalf ? (r2e + (size_t)hist_r[hidx] * 64)
                                     : (v2e + (size_t)hist_uv[hidx] * 64);
            uint4* drow = reinterpret_cast<uint4*>(hA0 + gr * SA + ghalf * 64);
#pragma unroll
            for (int gg = 0; gg < 4; gg++) {
                float4 f0 = *(const float4*)(src + gg * 16 + 0);
                float4 f1 = *(const float4*)(src + gg * 16 + 4);
                float4 f2 = *(const float4*)(src + gg * 16 + 8);
                float4 f3 = *(const float4*)(src + gg * 16 + 12);
                uint4 lo, hi;
                pack16(f0, f1, f2, f3, lo, hi);
                drow[gg * 2]     = lo;
                drow[gg * 2 + 1] = hi;
            }
        }
        __syncthreads();                               // (1) X + fUV ready

        // ---- uvatt[n][c] = uv[n] . A1_bot[:,c]  (LDS.128 weight reads) ----
        if (tid < 128) {
            int n = tid >> 6, c = tid & 63;
            const float* uvp = fUV + n * 64;
            const uint4* w4 = reinterpret_cast<const uint4*>(hA1W + c * SA + 64);
            float acc = 0.f;
#pragma unroll
            for (int gg = 0; gg < 4; gg++) {
                int jb = gg * 16;
                uint4 u0 = w4[gg * 2];
                uint4 u1 = w4[gg * 2 + 1];
                float2 q;
                q = __half22float2(*reinterpret_cast<__half2*>(&u0.x)); acc += q.x * uvp[jb + 0]  + q.y * uvp[jb + 1];
                q = __half22float2(*reinterpret_cast<__half2*>(&u0.y)); acc += q.x * uvp[jb + 8]  + q.y * uvp[jb + 9];
                q = __half22float2(*reinterpret_cast<__half2*>(&u0.z)); acc += q.x * uvp[jb + 2]  + q.y * uvp[jb + 3];
                q = __half22float2(*reinterpret_cast<__half2*>(&u0.w)); acc += q.x * uvp[jb + 10] + q.y * uvp[jb + 11];
                q = __half22float2(*reinterpret_cast<__half2*>(&u1.x)); acc += q.x * uvp[jb + 4]  + q.y * uvp[jb + 5];
                q = __half22float2(*reinterpret_cast<__half2*>(&u1.y)); acc += q.x * uvp[jb + 12] + q.y * uvp[jb + 13];
                q = __half22float2(*reinterpret_cast<__half2*>(&u1.z)); acc += q.x * uvp[jb + 6]  + q.y * uvp[jb + 7];
                q = __half22float2(*reinterpret_cast<__half2*>(&u1.w)); acc += q.x * uvp[jb + 14] + q.y * uvp[jb + 15];
            }
            fUVA[n * 64 + c] = acc;
        }

        float d[2][4][4];

        // ==== GEMM1: H = relu(X @ W1 + b1) -> hH ====
        zero_acc(d);
        gemm<8, SA, SA>(hA0, hW1, d, wq, wh, r, m);
        epi_store<SH>(d, fB1, hH, wq, wh, r, m);
        __syncthreads();                               // (2) H + uvatt ready

        // ==== GEMM2: o = relu(H @ W2 + b2) -> hA0 cols 0..63 ====
        zero_acc(d);
        gemm<4, SH, SH>(hH, hW2, d, wq, wh, r, m);
        epi_store<SA>(d, fB2, hA0, wq, wh, r, m);
        __syncthreads();                               // (3) o ready

        // ==== GEMM3: H2 = relu(o @ A1_top + ab1 + uvatt[n]) -> hH ====
        zero_acc(d);
        gemm<4, SA, SA>(hA0, hA1W, d, wq, wh, r, m);
        epi3(d, fAB1, fUVA, hH, wq, wh, r, m);
        __syncthreads();                               // (4) H2 ready

        // ==== GEMM4 + logit partial dot ====
        zero_acc(d);
        gemm<4, SH, SH>(hH, hA2W, d, wq, wh, r, m);
        {
            float p0[2] = {0.f, 0.f}, p1[2] = {0.f, 0.f};
#pragma unroll
            for (int mt = 0; mt < 2; mt++)
#pragma unroll
                for (int nt = 0; nt < 4; nt++) {
                    int c0 = wh * 32 + nt * 8 + 2 * m;
                    float w30 = fA3[c0], w31 = fA3[c0 + 1];
                    float bb0 = fAB2[c0], bb1 = fAB2[c0 + 1];
                    p0[mt] += fmaxf(d[mt][nt][0] + bb0, 0.f) * w30
                            + fmaxf(d[mt][nt][1] + bb1, 0.f) * w31;
                    p1[mt] += fmaxf(d[mt][nt][2] + bb0, 0.f) * w30
                            + fmaxf(d[mt][nt][3] + bb1, 0.f) * w31;
                }
#pragma unroll
            for (int off = 1; off <= 2; off <<= 1) {
#pragma unroll
                for (int mt = 0; mt < 2; mt++) {
                    p0[mt] += __shfl_xor_sync(0xffffffffu, p0[mt], off);
                    p1[mt] += __shfl_xor_sync(0xffffffffu, p1[mt], off);
                }
            }
            if (m == 0) {
#pragma unroll
                for (int mt = 0; mt < 2; mt++) {
                    int row = wq * 32 + mt * 16 + r;
                    fLGP[wh * 128 + row] = p0[mt];
                    fLGP[wh * 128 + row + 8] = p1[mt];
                }
            }
        }
        __syncthreads();                               // (5) logit partials ready

        // ---- softmax(50) + weighted sum of o (fp16 from A0) ----
        if (tid < 128) {
            const float* lgA = fLGP + sn * LHIST;
            const float* lgB = fLGP + 128 + sn * LHIST;
            const __half* ob = hA0 + sn * LHIST * SA + sdo;
            float mx = -1e30f;
#pragma unroll 10
            for (int l = 0; l < LHIST; l++) mx = fmaxf(mx, lgA[l] + lgB[l]);
            float s = 0.f, acc = 0.f;
#pragma unroll 10
            for (int l = 0; l < LHIST; l++) {
                float e = __expf(lgA[l] + lgB[l] - mx);
                s += e;
                acc += e * __half2float(ob[l * SA]);
            }
            out[(size_t)(b0 + sn) * 64 + sd] = acc / s;
        }
        __syncthreads();                               // (6) protect A0/LGP/UV
    }
}

extern "C" void kernel_launch(void* const* d_in, const int* in_sizes, int n_in,
                              void* d_out, int out_size) {
    const int*   nodes = (const int*)d_in[0];
    const int*   huv   = (const int*)d_in[1];
    const int*   hr    = (const int*)d_in[2];
    const float* v2e   = (const float*)d_in[3];
    const float* u2e   = (const float*)d_in[4];
    const float* r2e   = (const float*)d_in[5];
    const float* w1    = (const float*)d_in[6];
    const float* b1    = (const float*)d_in[7];
    const float* w2    = (const float*)d_in[8];
    const float* b2    = (const float*)d_in[9];
    const float* a1w   = (const float*)d_in[10];
    const float* a1b   = (const float*)d_in[11];
    const float* a2w   = (const float*)d_in[12];
    const float* a2b   = (const float*)d_in[13];
    const float* a3w   = (const float*)d_in[14];
    const float* a3b   = (const float*)d_in[15];
    float* out = (float*)d_out;

    const int B = in_sizes[0];
    const int ngroups = B / NB;

    static int attr_set = 0;
    if (!attr_set) {
        cudaFuncSetAttribute(uv_agg_h3, cudaFuncAttributeMaxDynamicSharedMemorySize, SMEM_BYTES);
        attr_set = 1;
    }
    uv_agg_h3<<<296, TPB, SMEM_BYTES>>>(nodes, huv, hr, v2e, u2e, r2e,
                                        w1, b1, w2, b2, a1w, a1b, a2w, a2b,
                                        a3w, a3b, out, ngroups);
}

// round 7
// speedup vs baseline: 1.1087x; 1.1087x over previous
#include <cuda_runtime.h>
#include <cuda_fp16.h>
#include <cstdint>

// ============================================================================
// GraphRec UV_Aggregator — warp-autonomous mma.sync fp16 kernel.
// compute_103-safe. 296 persistent CTAs x 128 threads, 2 CTAs/SM.
// Each warp owns 32 rows end-to-end through the whole MLP/attention chain
// (row-local GEMMs -> only __syncwarp between stages). 3 block syncs/group.
// Warp computes 32 rows x all 64 cols: d[2 m16][8 n8][4].
// ============================================================================

#define TPB   128
#define NB    2
#define LHIST 50
#define VROWS 100
#define SA    136    // halves stride, 128-k buffers
#define SH    72     // halves stride, 64-k buffers

// ---- smem byte offsets ----
#define O_A0   0u        // 128 x SA halves : X, later o in cols 0..63
#define O_H    34816u    // 128 x SH halves : hidden / H2
#define O_W1   53248u    // 64 x SA halves
#define O_A1W  70656u    // 64 x SA halves (A1_top k 0..63, A1_bot k 64..127)
#define O_W2   88064u    // 64 x SH halves
#define O_A2W  97280u
#define O_B1   106496u
#define O_B2   106752u
#define O_AB1  107008u
#define O_AB2  107264u
#define O_A3   107520u
#define O_UVA  107776u   // 2 x 64 fp32 : uv @ A1_bot
#define O_LG   108288u   // 128 fp32 logits
#define SMEM_BYTES 108800u

__device__ __forceinline__ void mma16(float (&d)[4], uint32_t a0, uint32_t a1,
                                      uint32_t a2, uint32_t a3, uint32_t b0, uint32_t b1) {
    asm volatile(
        "mma.sync.aligned.m16n8k16.row.col.f32.f16.f16.f32 "
        "{%0,%1,%2,%3}, {%4,%5,%6,%7}, {%8,%9}, {%0,%1,%2,%3};"
        : "+f"(d[0]), "+f"(d[1]), "+f"(d[2]), "+f"(d[3])
        : "r"(a0), "r"(a1), "r"(a2), "r"(a3), "r"(b0), "r"(b1));
}

__device__ __forceinline__ uint32_t h2(float lo, float hi) {
    __half2 h = __floats2half2_rn(lo, hi);
    return *reinterpret_cast<uint32_t*>(&h);
}

// fp16 storage index of logical col c within a row (pair-permuted k16 groups)
__device__ __forceinline__ int offcol(int c) {
    int gg = c >> 4, kr = c & 15, p = kr >> 1;
    int slot = (p & 3) * 2 + (p >> 2);
    return gg * 16 + slot * 2 + (kr & 1);
}

// Full-width warp GEMM: d[2 m16][8 n8] += A(rows 32*wq..+31) @ B(all 64 n)^T
template <int KST, int SAs, int SBs>
__device__ __forceinline__ void gemm_fw(const __half* __restrict__ As,
                                        const __half* __restrict__ Bs,
                                        float (&d)[2][8][4],
                                        int wq, int r, int m) {
    const __half* pa = As + (wq * 32 + r) * SAs + m * 4;
    const __half* pb = Bs + r * SBs + m * 4;
#pragma unroll
    for (int g = 0; g < KST; g++) {
        uint2 aA = *(const uint2*)(pa + 16 * g);
        uint2 aB = *(const uint2*)(pa + 8 * SAs + 16 * g);
        uint2 aC = *(const uint2*)(pa + 16 * SAs + 16 * g);
        uint2 aD = *(const uint2*)(pa + 24 * SAs + 16 * g);
        uint2 bv[8];
#pragma unroll
        for (int nt = 0; nt < 8; nt++)
            bv[nt] = *(const uint2*)(pb + nt * 8 * SBs + 16 * g);
#pragma unroll
        for (int nt = 0; nt < 8; nt++) {
            mma16(d[0][nt], aA.x, aB.x, aA.y, aB.y, bv[nt].x, bv[nt].y);
            mma16(d[1][nt], aC.x, aD.x, aC.y, aD.y, bv[nt].x, bv[nt].y);
        }
    }
}

__device__ __forceinline__ void zero_acc(float (&d)[2][8][4]) {
#pragma unroll
    for (int i = 0; i < 2; i++)
#pragma unroll
        for (int j = 0; j < 8; j++)
#pragma unroll
            for (int k = 0; k < 4; k++) d[i][j][k] = 0.f;
}

// relu(d + bias) -> half k-storage (STS.64, nt-pairs merged)
template <int SD>
__device__ __forceinline__ void epi_fw(float (&d)[2][8][4], const float* __restrict__ bias,
                                       __half* __restrict__ dst,
                                       int wq, int r, int m) {
#pragma unroll
    for (int mt = 0; mt < 2; mt++) {
        int row0 = wq * 32 + mt * 16 + r;
#pragma unroll
        for (int np = 0; np < 4; np++) {
            int ca = np * 16 + 2 * m, cb = ca + 8;
            float ba0 = bias[ca], ba1 = bias[ca + 1];
            float bb0 = bias[cb], bb1 = bias[cb + 1];
            int hoff = np * 16 + m * 4;
            uint2 v0, v1;
            v0.x = h2(fmaxf(d[mt][2*np][0] + ba0, 0.f), fmaxf(d[mt][2*np][1] + ba1, 0.f));
            v0.y = h2(fmaxf(d[mt][2*np+1][0] + bb0, 0.f), fmaxf(d[mt][2*np+1][1] + bb1, 0.f));
            v1.x = h2(fmaxf(d[mt][2*np][2] + ba0, 0.f), fmaxf(d[mt][2*np][3] + ba1, 0.f));
            v1.y = h2(fmaxf(d[mt][2*np+1][2] + bb0, 0.f), fmaxf(d[mt][2*np+1][3] + bb1, 0.f));
            *reinterpret_cast<uint2*>(dst + row0 * SD + hoff) = v0;
            *reinterpret_cast<uint2*>(dst + (row0 + 8) * SD + hoff) = v1;
        }
    }
}

// epi3: relu(d + ab1 + uvatt[node(row)]) -> half k-storage
__device__ __forceinline__ void epi3_fw(float (&d)[2][8][4], const float* __restrict__ bias,
                                        const float* __restrict__ uva,
                                        __half* __restrict__ dst,
                                        int wq, int r, int m) {
#pragma unroll
    for (int mt = 0; mt < 2; mt++) {
        int row0 = wq * 32 + mt * 16 + r;
        int na = (row0 >= LHIST) ? 1 : 0;
        int nb = (row0 + 8 >= LHIST) ? 1 : 0;
#pragma unroll
        for (int np = 0; np < 4; np++) {
            int ca = np * 16 + 2 * m, cb = ca + 8;
            float ba0 = bias[ca], ba1 = bias[ca + 1];
            float bb0 = bias[cb], bb1 = bias[cb + 1];
            int hoff = np * 16 + m * 4;
            uint2 v0, v1;
            v0.x = h2(fmaxf(d[mt][2*np][0] + ba0 + uva[na*64+ca], 0.f),
                      fmaxf(d[mt][2*np][1] + ba1 + uva[na*64+ca+1], 0.f));
            v0.y = h2(fmaxf(d[mt][2*np+1][0] + bb0 + uva[na*64+cb], 0.f),
                      fmaxf(d[mt][2*np+1][1] + bb1 + uva[na*64+cb+1], 0.f));
            v1.x = h2(fmaxf(d[mt][2*np][2] + ba0 + uva[nb*64+ca], 0.f),
                      fmaxf(d[mt][2*np][3] + ba1 + uva[nb*64+ca+1], 0.f));
            v1.y = h2(fmaxf(d[mt][2*np+1][2] + bb0 + uva[nb*64+cb], 0.f),
                      fmaxf(d[mt][2*np+1][3] + bb1 + uva[nb*64+cb+1], 0.f));
            *reinterpret_cast<uint2*>(dst + row0 * SH + hoff) = v0;
            *reinterpret_cast<uint2*>(dst + (row0 + 8) * SH + hoff) = v1;
        }
    }
}

// stage weight W[K][64] (gmem row-major) -> half dst[n][k-storage].
__device__ __forceinline__ void stage_wh(__half* __restrict__ dst, const float* __restrict__ W,
                                         int K, int strh, int tid) {
    for (int idx = tid; idx < K * 64; idx += TPB) {
        int k = idx >> 6, n = idx & 63;
        dst[n * strh + offcol(k)] = __float2half_rn(W[idx]);
    }
}

// pack 16 floats of one k16-group into 2 uint4s (pair-permuted slot order)
__device__ __forceinline__ void pack16(const float4& f0, const float4& f1,
                                       const float4& f2, const float4& f3,
                                       uint4& lo, uint4& hi) {
    lo.x = h2(f0.x, f0.y);  lo.y = h2(f2.x, f2.y);
    lo.z = h2(f0.z, f0.w);  lo.w = h2(f2.z, f2.w);
    hi.x = h2(f1.x, f1.y);  hi.y = h2(f3.x, f3.y);
    hi.z = h2(f1.z, f1.w);  hi.w = h2(f3.z, f3.w);
}

__global__ __launch_bounds__(TPB, 2)
void uv_agg_w(const int* __restrict__ nodes,
              const int* __restrict__ hist_uv,
              const int* __restrict__ hist_r,
              const float* __restrict__ v2e,
              const float* __restrict__ u2e,
              const float* __restrict__ r2e,
              const float* __restrict__ w1, const float* __restrict__ b1,
              const float* __restrict__ w2, const float* __restrict__ b2,
              const float* __restrict__ a1w, const float* __restrict__ a1b,
              const float* __restrict__ a2w, const float* __restrict__ a2b,
              const float* __restrict__ a3w, const float* __restrict__ a3b,
              float* __restrict__ out, int ngroups) {
    extern __shared__ char smem[];
    __half* hA0  = reinterpret_cast<__half*>(smem + O_A0);
    __half* hH   = reinterpret_cast<__half*>(smem + O_H);
    __half* hW1  = reinterpret_cast<__half*>(smem + O_W1);
    __half* hA1W = reinterpret_cast<__half*>(smem + O_A1W);
    __half* hW2  = reinterpret_cast<__half*>(smem + O_W2);
    __half* hA2W = reinterpret_cast<__half*>(smem + O_A2W);
    float* fB1  = reinterpret_cast<float*>(smem + O_B1);
    float* fB2  = reinterpret_cast<float*>(smem + O_B2);
    float* fAB1 = reinterpret_cast<float*>(smem + O_AB1);
    float* fAB2 = reinterpret_cast<float*>(smem + O_AB2);
    float* fA3  = reinterpret_cast<float*>(smem + O_A3);
    float* fUVA = reinterpret_cast<float*>(smem + O_UVA);
    float* fLG  = reinterpret_cast<float*>(smem + O_LG);

    const int tid = threadIdx.x;
    const int wid = tid >> 5, lane = tid & 31;
    const int r = lane >> 2, m = lane & 3;

    // ---- stage weights + biases once per CTA ----
    stage_wh(hW1, w1, 128, SA, tid);
    stage_wh(hA1W, a1w, 128, SA, tid);   // k 0..63 = A1_top, k 64..127 = A1_bot
    stage_wh(hW2, w2, 64, SH, tid);
    stage_wh(hA2W, a2w, 64, SH, tid);
    if (tid < 64) {
        fB1[tid]  = b1[tid];
        fB2[tid]  = b2[tid];
        fAB1[tid] = a1b[tid];
        fAB2[tid] = a2b[tid];
        fA3[tid]  = a3w[tid];
    }
    __syncthreads();

    const int sn = tid >> 6;       // softmax: node
    const int sd = tid & 63;       // softmax: dim
    const int sdo = offcol(sd);

    for (int g = blockIdx.x; g < ngroups; g += gridDim.x) {
        const int b0 = g * NB;

        // ---- per-warp gather: own row = wid*32 + lane ----
        {
            int grow = wid * 32 + lane;
            if (grow < VROWS) {
                int gn = (grow >= LHIST) ? 1 : 0;
                int gl = grow - gn * LHIST;
                int hidx = (b0 + gn) * LHIST + gl;
                const float* su = v2e + (size_t)hist_uv[hidx] * 64;
                const float* sr = r2e + (size_t)hist_r[hidx] * 64;
                uint4* drow = reinterpret_cast<uint4*>(hA0 + grow * SA);
#pragma unroll
                for (int gg = 0; gg < 4; gg++) {
                    float4 f0 = *(const float4*)(su + gg * 16 + 0);
                    float4 f1 = *(const float4*)(su + gg * 16 + 4);
                    float4 f2 = *(const float4*)(su + gg * 16 + 8);
                    float4 f3 = *(const float4*)(su + gg * 16 + 12);
                    uint4 lo, hi;
                    pack16(f0, f1, f2, f3, lo, hi);
                    drow[gg * 2] = lo; drow[gg * 2 + 1] = hi;
                }
#pragma unroll
                for (int gg = 0; gg < 4; gg++) {
                    float4 f0 = *(const float4*)(sr + gg * 16 + 0);
                    float4 f1 = *(const float4*)(sr + gg * 16 + 4);
                    float4 f2 = *(const float4*)(sr + gg * 16 + 8);
                    float4 f3 = *(const float4*)(sr + gg * 16 + 12);
                    uint4 lo, hi;
                    pack16(f0, f1, f2, f3, lo, hi);
                    drow[8 + gg * 2] = lo; drow[8 + gg * 2 + 1] = hi;
                }
            }
        }

        // ---- uvatt: warps 0,1 compute uv[n] . A1_bot (uv read from gmem, bcast) ----
        if (wid < 2) {
            const float* uvg = u2e + (size_t)nodes[b0 + wid] * 64;
#pragma unroll
            for (int cc = 0; cc < 2; cc++) {
                int c = lane + cc * 32;
                const uint4* w4 = reinterpret_cast<const uint4*>(hA1W + c * SA + 64);
                float acc = 0.f;
#pragma unroll
                for (int gg = 0; gg < 4; gg++) {
                    const float* u = uvg + gg * 16;
                    float4 u0 = *(const float4*)(u + 0);
                    float4 u1 = *(const float4*)(u + 4);
                    float4 u2v = *(const float4*)(u + 8);
                    float4 u3 = *(const float4*)(u + 12);
                    uint4 wa = w4[gg * 2], wb = w4[gg * 2 + 1];
                    float2 q;
                    q = __half22float2(*reinterpret_cast<__half2*>(&wa.x)); acc += q.x*u0.x + q.y*u0.y;
                    q = __half22float2(*reinterpret_cast<__half2*>(&wa.y)); acc += q.x*u2v.x + q.y*u2v.y;
                    q = __half22float2(*reinterpret_cast<__half2*>(&wa.z)); acc += q.x*u0.z + q.y*u0.w;
                    q = __half22float2(*reinterpret_cast<__half2*>(&wa.w)); acc += q.x*u2v.z + q.y*u2v.w;
                    q = __half22float2(*reinterpret_cast<__half2*>(&wb.x)); acc += q.x*u1.x + q.y*u1.y;
                    q = __half22float2(*reinterpret_cast<__half2*>(&wb.y)); acc += q.x*u3.x + q.y*u3.y;
                    q = __half22float2(*reinterpret_cast<__half2*>(&wb.z)); acc += q.x*u1.z + q.y*u1.w;
                    q = __half22float2(*reinterpret_cast<__half2*>(&wb.w)); acc += q.x*u3.z + q.y*u3.w;
                }
                fUVA[wid * 64 + c] = acc;
            }
        }
        __syncthreads();                               // S1: uvatt + X ready

        float d[2][8][4];

        // ==== GEMM1: H = relu(X @ W1 + b1) ====
        zero_acc(d);
        gemm_fw<8, SA, SA>(hA0, hW1, d, wid, r, m);
        epi_fw<SH>(d, fB1, hH, wid, r, m);
        __syncwarp();

        // ==== GEMM2: o = relu(H @ W2 + b2) -> A0 cols 0..63 ====
        zero_acc(d);
        gemm_fw<4, SH, SH>(hH, hW2, d, wid, r, m);
        epi_fw<SA>(d, fB2, hA0, wid, r, m);
        __syncwarp();

        // ==== GEMM3: H2 = relu(o @ A1_top + ab1 + uvatt[n]) ====
        zero_acc(d);
        gemm_fw<4, SA, SA>(hA0, hA1W, d, wid, r, m);
        epi3_fw(d, fAB1, fUVA, hH, wid, r, m);
        __syncwarp();

        // ==== GEMM4 + full logit dot ====
        zero_acc(d);
        gemm_fw<4, SH, SH>(hH, hA2W, d, wid, r, m);
        {
            float p0[2] = {0.f, 0.f}, p1[2] = {0.f, 0.f};
#pragma unroll
            for (int mt = 0; mt < 2; mt++)
#pragma unroll
                for (int nt = 0; nt < 8; nt++) {
                    int c0 = nt * 8 + 2 * m;
                    float w30 = fA3[c0], w31 = fA3[c0 + 1];
                    float bb0 = fAB2[c0], bb1 = fAB2[c0 + 1];
                    p0[mt] += fmaxf(d[mt][nt][0] + bb0, 0.f) * w30
                            + fmaxf(d[mt][nt][1] + bb1, 0.f) * w31;
                    p1[mt] += fmaxf(d[mt][nt][2] + bb0, 0.f) * w30
                            + fmaxf(d[mt][nt][3] + bb1, 0.f) * w31;
                }
#pragma unroll
            for (int off = 1; off <= 2; off <<= 1) {
#pragma unroll
                for (int mt = 0; mt < 2; mt++) {
                    p0[mt] += __shfl_xor_sync(0xffffffffu, p0[mt], off);
                    p1[mt] += __shfl_xor_sync(0xffffffffu, p1[mt], off);
                }
            }
            if (m == 0) {
#pragma unroll
                for (int mt = 0; mt < 2; mt++) {
                    int row = wid * 32 + mt * 16 + r;
                    fLG[row] = p0[mt];
                    fLG[row + 8] = p1[mt];
                }
            }
        }
        __syncthreads();                               // S2: logits + o ready

        // ---- softmax(50) + weighted sum of o (fp16 from A0) ----
        {
            const float* lg = fLG + sn * LHIST;
            const __half* ob = hA0 + sn * LHIST * SA + sdo;
            float mx = -1e30f;
#pragma unroll 10
            for (int l = 0; l < LHIST; l++) mx = fmaxf(mx, lg[l]);
            float s = 0.f, acc = 0.f;
#pragma unroll 10
            for (int l = 0; l < LHIST; l++) {
                float e = __expf(lg[l] - mx);
                s += e;
                acc += e * __half2float(ob[l * SA]);
            }
            out[(size_t)(b0 + sn) * 64 + sd] = acc / s;
        }
        __syncthreads();                               // S3: A0/fLG free
    }
}

extern "C" void kernel_launch(void* const* d_in, const int* in_sizes, int n_in,
                              void* d_out, int out_size) {
    const int*   nodes = (const int*)d_in[0];
    const int*   huv   = (const int*)d_in[1];
    const int*   hr    = (const int*)d_in[2];
    const float* v2e   = (const float*)d_in[3];
    const float* u2e   = (const float*)d_in[4];
    const float* r2e   = (const float*)d_in[5];
    const float* w1    = (const float*)d_in[6];
    const float* b1    = (const float*)d_in[7];
    const float* w2    = (const float*)d_in[8];
    const float* b2    = (const float*)d_in[9];
    const float* a1w   = (const float*)d_in[10];
    const float* a1b   = (const float*)d_in[11];
    const float* a2w   = (const float*)d_in[12];
    const float* a2b   = (const float*)d_in[13];
    const float* a3w   = (const float*)d_in[14];
    const float* a3b   = (const float*)d_in[15];
    float* out = (float*)d_out;

    const int B = in_sizes[0];
    const int ngroups = B / NB;

    static int attr_set = 0;
    if (!attr_set) {
        cudaFuncSetAttribute(uv_agg_w, cudaFuncAttributeMaxDynamicSharedMemorySize, SMEM_BYTES);
        attr_set = 1;
    }
    uv_agg_w<<<296, TPB, SMEM_BYTES>>>(nodes, huv, hr, v2e, u2e, r2e,
                                       w1, b1, w2, b2, a1w, a1b, a2w, a2b,
                                       a3w, a3b, out, ngroups);
}

// round 8
// speedup vs baseline: 1.2402x; 1.1186x over previous
#include <cuda_runtime.h>
#include <cuda_fp16.h>
#include <cstdint>

// ============================================================================
// GraphRec UV_Aggregator — register-chained mma.sync fp16 kernel.
// compute_103-safe. 296 persistent CTAs x 128 threads, 2 CTAs/SM (~90KB smem).
// Each warp owns 32 rows end-to-end. GEMM1 reads X from smem; GEMM2/3/4 take
// their A-operands DIRECTLY from the previous accumulators (m16n8k16 accum
// layout == next A-fragment layout after half2 packing) — no smem round-trips.
// ============================================================================

#define TPB   128
#define NB    2
#define LHIST 50
#define VROWS 100
#define SA    136    // halves stride, 128-k buffers
#define SH    72     // halves stride, 64-k buffers

// ---- smem byte offsets ----
#define O_A0   0u        // 128 x SA halves : X (cols 0..127), later o in cols 0..63
#define O_W1   34816u    // 64 x SA halves
#define O_A1W  52224u    // 64 x SA halves (A1_top k 0..63, A1_bot k 64..127)
#define O_W2   69632u    // 64 x SH halves
#define O_A2W  78848u    // 64 x SH halves
#define O_B1   88064u
#define O_B2   88320u
#define O_AB1  88576u
#define O_AB2  88832u
#define O_A3   89088u
#define O_UVA  89344u    // 2 x 64 fp32 : uv @ A1_bot
#define O_LG   89856u    // 128 fp32 logits
#define SMEM_BYTES 90368u

__device__ __forceinline__ void mma16(float (&d)[4], uint32_t a0, uint32_t a1,
                                      uint32_t a2, uint32_t a3, uint32_t b0, uint32_t b1) {
    asm volatile(
        "mma.sync.aligned.m16n8k16.row.col.f32.f16.f16.f32 "
        "{%0,%1,%2,%3}, {%4,%5,%6,%7}, {%8,%9}, {%0,%1,%2,%3};"
        : "+f"(d[0]), "+f"(d[1]), "+f"(d[2]), "+f"(d[3])
        : "r"(a0), "r"(a1), "r"(a2), "r"(a3), "r"(b0), "r"(b1));
}

__device__ __forceinline__ uint32_t h2(float lo, float hi) {
    __half2 h = __floats2half2_rn(lo, hi);
    return *reinterpret_cast<uint32_t*>(&h);
}

// fp16 storage index of logical col c within a row (pair-permuted k16 groups)
__device__ __forceinline__ int offcol(int c) {
    int gg = c >> 4, kr = c & 15, p = kr >> 1;
    int slot = (p & 3) * 2 + (p >> 2);
    return gg * 16 + slot * 2 + (kr & 1);
}

// GEMM1 (A from smem): d[2 m16][8 n8] += A(rows 32*wq..+31) @ B(all 64 n)^T
template <int KST, int SAs, int SBs>
__device__ __forceinline__ void gemm_fw(const __half* __restrict__ As,
                                        const __half* __restrict__ Bs,
                                        float (&d)[2][8][4],
                                        int wq, int r, int m) {
    const __half* pa = As + (wq * 32 + r) * SAs + m * 4;
    const __half* pb = Bs + r * SBs + m * 4;
#pragma unroll
    for (int g = 0; g < KST; g++) {
        uint2 aA = *(const uint2*)(pa + 16 * g);
        uint2 aB = *(const uint2*)(pa + 8 * SAs + 16 * g);
        uint2 aC = *(const uint2*)(pa + 16 * SAs + 16 * g);
        uint2 aD = *(const uint2*)(pa + 24 * SAs + 16 * g);
        uint2 bv[8];
#pragma unroll
        for (int nt = 0; nt < 8; nt++)
            bv[nt] = *(const uint2*)(pb + nt * 8 * SBs + 16 * g);
#pragma unroll
        for (int nt = 0; nt < 8; nt++) {
            mma16(d[0][nt], aA.x, aB.x, aA.y, aB.y, bv[nt].x, bv[nt].y);
            mma16(d[1][nt], aC.x, aD.x, aC.y, aD.y, bv[nt].x, bv[nt].y);
        }
    }
}

// register-A GEMM (K=64): a[mt][kg][0..3] are A-fragments, B from smem.
template <int SBs>
__device__ __forceinline__ void gemm_regA(const __half* __restrict__ Bs,
                                          const uint32_t (&a)[2][4][4],
                                          float (&d)[2][8][4], int r, int m) {
    const __half* pb = Bs + r * SBs + m * 4;
#pragma unroll
    for (int kg = 0; kg < 4; kg++) {
        uint2 bv[8];
#pragma unroll
        for (int nt = 0; nt < 8; nt++)
            bv[nt] = *(const uint2*)(pb + nt * 8 * SBs + 16 * kg);
#pragma unroll
        for (int nt = 0; nt < 8; nt++) {
            mma16(d[0][nt], a[0][kg][0], a[0][kg][1], a[0][kg][2], a[0][kg][3],
                  bv[nt].x, bv[nt].y);
            mma16(d[1][nt], a[1][kg][0], a[1][kg][1], a[1][kg][2], a[1][kg][3],
                  bv[nt].x, bv[nt].y);
        }
    }
}

__device__ __forceinline__ void zero_acc(float (&d)[2][8][4]) {
#pragma unroll
    for (int i = 0; i < 2; i++)
#pragma unroll
        for (int j = 0; j < 8; j++)
#pragma unroll
            for (int k = 0; k < 4; k++) d[i][j][k] = 0.f;
}

// accum -> next-stage A-fragments: h[mt][kg] = relu(d + bias) packed half2.
__device__ __forceinline__ void cvt_stage(const float (&d)[2][8][4],
                                          const float* __restrict__ bias,
                                          uint32_t (&h)[2][4][4], int m) {
#pragma unroll
    for (int kg = 0; kg < 4; kg++) {
        int ca = kg * 16 + 2 * m, cb = ca + 8;
        float2 bA = *(const float2*)(bias + ca);
        float2 bB = *(const float2*)(bias + cb);
#pragma unroll
        for (int mt = 0; mt < 2; mt++) {
            h[mt][kg][0] = h2(fmaxf(d[mt][2*kg][0] + bA.x, 0.f),
                              fmaxf(d[mt][2*kg][1] + bA.y, 0.f));
            h[mt][kg][1] = h2(fmaxf(d[mt][2*kg][2] + bA.x, 0.f),
                              fmaxf(d[mt][2*kg][3] + bA.y, 0.f));
            h[mt][kg][2] = h2(fmaxf(d[mt][2*kg+1][0] + bB.x, 0.f),
                              fmaxf(d[mt][2*kg+1][1] + bB.y, 0.f));
            h[mt][kg][3] = h2(fmaxf(d[mt][2*kg+1][2] + bB.x, 0.f),
                              fmaxf(d[mt][2*kg+1][3] + bB.y, 0.f));
        }
    }
}

// stage-3 variant: + uvatt[node(row)]
__device__ __forceinline__ void cvt_stage3(const float (&d)[2][8][4],
                                           const float* __restrict__ bias,
                                           const float* __restrict__ uva,
                                           uint32_t (&h)[2][4][4],
                                           int wq, int r, int m) {
#pragma unroll
    for (int mt = 0; mt < 2; mt++) {
        int row0 = wq * 32 + mt * 16 + r;
        const float* ua = uva + ((row0 >= LHIST) ? 64 : 0);       // rows r
        const float* ub = uva + ((row0 + 8 >= LHIST) ? 64 : 0);   // rows r+8
#pragma unroll
        for (int kg = 0; kg < 4; kg++) {
            int ca = kg * 16 + 2 * m, cb = ca + 8;
            float2 bA = *(const float2*)(bias + ca);
            float2 bB = *(const float2*)(bias + cb);
            float2 uaA = *(const float2*)(ua + ca);
            float2 uaB = *(const float2*)(ua + cb);
            float2 ubA = *(const float2*)(ub + ca);
            float2 ubB = *(const float2*)(ub + cb);
            h[mt][kg][0] = h2(fmaxf(d[mt][2*kg][0] + bA.x + uaA.x, 0.f),
                              fmaxf(d[mt][2*kg][1] + bA.y + uaA.y, 0.f));
            h[mt][kg][1] = h2(fmaxf(d[mt][2*kg][2] + bA.x + ubA.x, 0.f),
                              fmaxf(d[mt][2*kg][3] + bA.y + ubA.y, 0.f));
            h[mt][kg][2] = h2(fmaxf(d[mt][2*kg+1][0] + bB.x + uaB.x, 0.f),
                              fmaxf(d[mt][2*kg+1][1] + bB.y + uaB.y, 0.f));
            h[mt][kg][3] = h2(fmaxf(d[mt][2*kg+1][2] + bB.x + ubB.x, 0.f),
                              fmaxf(d[mt][2*kg+1][3] + bB.y + ubB.y, 0.f));
        }
    }
}

// store o fragments to A0 (k-storage layout) for the softmax weighted sum
__device__ __forceinline__ void store_o(const uint32_t (&h)[2][4][4],
                                        __half* __restrict__ dst,
                                        int wq, int r, int m) {
#pragma unroll
    for (int mt = 0; mt < 2; mt++) {
        int row0 = wq * 32 + mt * 16 + r;
#pragma unroll
        for (int kg = 0; kg < 4; kg++) {
            int hoff = kg * 16 + m * 4;
            *reinterpret_cast<uint2*>(dst + row0 * SA + hoff) =
                make_uint2(h[mt][kg][0], h[mt][kg][2]);        // rows r
            *reinterpret_cast<uint2*>(dst + (row0 + 8) * SA + hoff) =
                make_uint2(h[mt][kg][1], h[mt][kg][3]);        // rows r+8
        }
    }
}

// stage weight W[K][64] (gmem row-major) -> half dst[n][k-storage].
__device__ __forceinline__ void stage_wh(__half* __restrict__ dst, const float* __restrict__ W,
                                         int K, int strh, int tid) {
    for (int idx = tid; idx < K * 64; idx += TPB) {
        int k = idx >> 6, n = idx & 63;
        dst[n * strh + offcol(k)] = __float2half_rn(W[idx]);
    }
}

// pack 16 floats of one k16-group into 2 uint4s (pair-permuted slot order)
__device__ __forceinline__ void pack16(const float4& f0, const float4& f1,
                                       const float4& f2, const float4& f3,
                                       uint4& lo, uint4& hi) {
    lo.x = h2(f0.x, f0.y);  lo.y = h2(f2.x, f2.y);
    lo.z = h2(f0.z, f0.w);  lo.w = h2(f2.z, f2.w);
    hi.x = h2(f1.x, f1.y);  hi.y = h2(f3.x, f3.y);
    hi.z = h2(f1.z, f1.w);  hi.w = h2(f3.z, f3.w);
}

__global__ __launch_bounds__(TPB, 2)
void uv_agg_rc(const int* __restrict__ nodes,
               const int* __restrict__ hist_uv,
               const int* __restrict__ hist_r,
               const float* __restrict__ v2e,
               const float* __restrict__ u2e,
               const float* __restrict__ r2e,
               const float* __restrict__ w1, const float* __restrict__ b1,
               const float* __restrict__ w2, const float* __restrict__ b2,
               const float* __restrict__ a1w, const float* __restrict__ a1b,
               const float* __restrict__ a2w, const float* __restrict__ a2b,
               const float* __restrict__ a3w, const float* __restrict__ a3b,
               float* __restrict__ out, int ngroups) {
    extern __shared__ char smem[];
    __half* hA0  = reinterpret_cast<__half*>(smem + O_A0);
    __half* hW1  = reinterpret_cast<__half*>(smem + O_W1);
    __half* hA1W = reinterpret_cast<__half*>(smem + O_A1W);
    __half* hW2  = reinterpret_cast<__half*>(smem + O_W2);
    __half* hA2W = reinterpret_cast<__half*>(smem + O_A2W);
    float* fB1  = reinterpret_cast<float*>(smem + O_B1);
    float* fB2  = reinterpret_cast<float*>(smem + O_B2);
    float* fAB1 = reinterpret_cast<float*>(smem + O_AB1);
    float* fAB2 = reinterpret_cast<float*>(smem + O_AB2);
    float* fA3  = reinterpret_cast<float*>(smem + O_A3);
    float* fUVA = reinterpret_cast<float*>(smem + O_UVA);
    float* fLG  = reinterpret_cast<float*>(smem + O_LG);

    const int tid = threadIdx.x;
    const int wid = tid >> 5, lane = tid & 31;
    const int r = lane >> 2, m = lane & 3;

    // ---- stage weights + biases once per CTA ----
    stage_wh(hW1, w1, 128, SA, tid);
    stage_wh(hA1W, a1w, 128, SA, tid);   // k 0..63 = A1_top, k 64..127 = A1_bot
    stage_wh(hW2, w2, 64, SH, tid);
    stage_wh(hA2W, a2w, 64, SH, tid);
    if (tid < 64) {
        fB1[tid]  = b1[tid];
        fB2[tid]  = b2[tid];
        fAB1[tid] = a1b[tid];
        fAB2[tid] = a2b[tid];
        fA3[tid]  = a3w[tid];
    }
    __syncthreads();

    const int sn = tid >> 6;       // softmax: node
    const int sd = tid & 63;       // softmax: dim
    const int sdo = offcol(sd);

    for (int g = blockIdx.x; g < ngroups; g += gridDim.x) {
        const int b0 = g * NB;

        // ---- per-warp gather: own row = wid*32 + lane ----
        {
            int grow = wid * 32 + lane;
            if (grow < VROWS) {
                int gn = (grow >= LHIST) ? 1 : 0;
                int gl = grow - gn * LHIST;
                int hidx = (b0 + gn) * LHIST + gl;
                const float* su = v2e + (size_t)hist_uv[hidx] * 64;
                const float* sr = r2e + (size_t)hist_r[hidx] * 64;
                uint4* drow = reinterpret_cast<uint4*>(hA0 + grow * SA);
#pragma unroll
                for (int gg = 0; gg < 4; gg++) {
                    float4 f0 = *(const float4*)(su + gg * 16 + 0);
                    float4 f1 = *(const float4*)(su + gg * 16 + 4);
                    float4 f2 = *(const float4*)(su + gg * 16 + 8);
                    float4 f3 = *(const float4*)(su + gg * 16 + 12);
                    uint4 lo, hi;
                    pack16(f0, f1, f2, f3, lo, hi);
                    drow[gg * 2] = lo; drow[gg * 2 + 1] = hi;
                }
#pragma unroll
                for (int gg = 0; gg < 4; gg++) {
                    float4 f0 = *(const float4*)(sr + gg * 16 + 0);
                    float4 f1 = *(const float4*)(sr + gg * 16 + 4);
                    float4 f2 = *(const float4*)(sr + gg * 16 + 8);
                    float4 f3 = *(const float4*)(sr + gg * 16 + 12);
                    uint4 lo, hi;
                    pack16(f0, f1, f2, f3, lo, hi);
                    drow[8 + gg * 2] = lo; drow[8 + gg * 2 + 1] = hi;
                }
            }
        }

        // ---- uvatt: warps 0,1 compute uv[n] . A1_bot (uv read from gmem) ----
        if (wid < 2) {
            const float* uvg = u2e + (size_t)nodes[b0 + wid] * 64;
#pragma unroll
            for (int cc = 0; cc < 2; cc++) {
                int c = lane + cc * 32;
                const uint4* w4 = reinterpret_cast<const uint4*>(hA1W + c * SA + 64);
                float acc = 0.f;
#pragma unroll
                for (int gg = 0; gg < 4; gg++) {
                    const float* u = uvg + gg * 16;
                    float4 u0 = *(const float4*)(u + 0);
                    float4 u1 = *(const float4*)(u + 4);
                    float4 u2v = *(const float4*)(u + 8);
                    float4 u3 = *(const float4*)(u + 12);
                    uint4 wa = w4[gg * 2], wb = w4[gg * 2 + 1];
                    float2 q;
                    q = __half22float2(*reinterpret_cast<__half2*>(&wa.x)); acc += q.x*u0.x + q.y*u0.y;
                    q = __half22float2(*reinterpret_cast<__half2*>(&wa.y)); acc += q.x*u2v.x + q.y*u2v.y;
                    q = __half22float2(*reinterpret_cast<__half2*>(&wa.z)); acc += q.x*u0.z + q.y*u0.w;
                    q = __half22float2(*reinterpret_cast<__half2*>(&wa.w)); acc += q.x*u2v.z + q.y*u2v.w;
                    q = __half22float2(*reinterpret_cast<__half2*>(&wb.x)); acc += q.x*u1.x + q.y*u1.y;
                    q = __half22float2(*reinterpret_cast<__half2*>(&wb.y)); acc += q.x*u3.x + q.y*u3.y;
                    q = __half22float2(*reinterpret_cast<__half2*>(&wb.z)); acc += q.x*u1.z + q.y*u1.w;
                    q = __half22float2(*reinterpret_cast<__half2*>(&wb.w)); acc += q.x*u3.z + q.y*u3.w;
                }
                fUVA[wid * 64 + c] = acc;
            }
        }
        __syncthreads();                               // S1: uvatt + X ready

        float d[2][8][4];
        uint32_t h[2][4][4];

        // ==== GEMM1: H = relu(X @ W1 + b1) — A from smem, result to regs ====
        zero_acc(d);
        gemm_fw<8, SA, SA>(hA0, hW1, d, wid, r, m);
        cvt_stage(d, fB1, h, m);

        // ==== GEMM2: o = relu(H @ W2 + b2) — A from regs ====
        zero_acc(d);
        gemm_regA<SH>(hW2, h, d, r, m);
        cvt_stage(d, fB2, h, m);
        store_o(h, hA0, wid, r, m);        // warp-private rows; no sync needed

        // ==== GEMM3: H2 = relu(o @ A1_top + ab1 + uvatt[n]) — A from regs ====
        zero_acc(d);
        gemm_regA<SA>(hA1W, h, d, r, m);
        cvt_stage3(d, fAB1, fUVA, h, wid, r, m);

        // ==== GEMM4 + full logit dot ====
        zero_acc(d);
        gemm_regA<SH>(hA2W, h, d, r, m);
        {
            float p0[2] = {0.f, 0.f}, p1[2] = {0.f, 0.f};
#pragma unroll
            for (int mt = 0; mt < 2; mt++)
#pragma unroll
                for (int nt = 0; nt < 8; nt++) {
                    int c0 = nt * 8 + 2 * m;
                    float w30 = fA3[c0], w31 = fA3[c0 + 1];
                    float bb0 = fAB2[c0], bb1 = fAB2[c0 + 1];
                    p0[mt] += fmaxf(d[mt][nt][0] + bb0, 0.f) * w30
                            + fmaxf(d[mt][nt][1] + bb1, 0.f) * w31;
                    p1[mt] += fmaxf(d[mt][nt][2] + bb0, 0.f) * w30
                            + fmaxf(d[mt][nt][3] + bb1, 0.f) * w31;
                }
#pragma unroll
            for (int off = 1; off <= 2; off <<= 1) {
#pragma unroll
                for (int mt = 0; mt < 2; mt++) {
                    p0[mt] += __shfl_xor_sync(0xffffffffu, p0[mt], off);
                    p1[mt] += __shfl_xor_sync(0xffffffffu, p1[mt], off);
                }
            }
            if (m == 0) {
#pragma unroll
                for (int mt = 0; mt < 2; mt++) {
                    int row = wid * 32 + mt * 16 + r;
                    fLG[row] = p0[mt];
                    fLG[row + 8] = p1[mt];
                }
            }
        }
        __syncthreads();                               // S2: logits + o ready

        // ---- softmax(50) + weighted sum of o (fp16 from A0) ----
        {
            const float* lg = fLG + sn * LHIST;
            const __half* ob = hA0 + sn * LHIST * SA + sdo;
            float mx = -1e30f;
#pragma unroll 10
            for (int l = 0; l < LHIST; l++) mx = fmaxf(mx, lg[l]);
            float s = 0.f, acc = 0.f;
#pragma unroll 10
            for (int l = 0; l < LHIST; l++) {
                float e = __expf(lg[l] - mx);
                s += e;
                acc += e * __half2float(ob[l * SA]);
            }
            out[(size_t)(b0 + sn) * 64 + sd] = acc / s;
        }
        __syncthreads();                               // S3: A0/fLG free
    }
}

extern "C" void kernel_launch(void* const* d_in, const int* in_sizes, int n_in,
                              void* d_out, int out_size) {
    const int*   nodes = (const int*)d_in[0];
    const int*   huv   = (const int*)d_in[1];
    const int*   hr    = (const int*)d_in[2];
    const float* v2e   = (const float*)d_in[3];
    const float* u2e   = (const float*)d_in[4];
    const float* r2e   = (const float*)d_in[5];
    const float* w1    = (const float*)d_in[6];
    const float* b1    = (const float*)d_in[7];
    const float* w2    = (const float*)d_in[8];
    const float* b2    = (const float*)d_in[9];
    const float* a1w   = (const float*)d_in[10];
    const float* a1b   = (const float*)d_in[11];
    const float* a2w   = (const float*)d_in[12];
    const float* a2b   = (const float*)d_in[13];
    const float* a3w   = (const float*)d_in[14];
    const float* a3b   = (const float*)d_in[15];
    float* out = (float*)d_out;

    const int B = in_sizes[0];
    const int ngroups = B / NB;

    static int attr_set = 0;
    if (!attr_set) {
        cudaFuncSetAttribute(uv_agg_rc, cudaFuncAttributeMaxDynamicSharedMemorySize, SMEM_BYTES);
        attr_set = 1;
    }
    uv_agg_rc<<<296, TPB, SMEM_BYTES>>>(nodes, huv, hr, v2e, u2e, r2e,
                                        w1, b1, w2, b2, a1w, a1b, a2w, a2b,
                                        a3w, a3b, out, ngroups);
}

// round 9
// speedup vs baseline: 1.3594x; 1.0962x over previous
#include <cuda_runtime.h>
#include <cuda_fp16.h>
#include <cstdint>

// ============================================================================
// GraphRec UV_Aggregator — register-chained mma.sync fp16 kernel, 3 CTAs/SM.
// compute_103-safe. 444 persistent CTAs x 128 threads (~74KB smem each).
// Each warp owns 32 rows end-to-end. GEMM1 runs as two accumulating K=64
// passes (e_uv then e_r reusing one 64-col A0 tile); GEMM2/3/4 take A-operands
// directly from previous accumulators (no smem round-trips).
// ============================================================================

#define TPB   128
#define NB    2
#define LHIST 50
#define VROWS 100
#define SA    136    // halves stride, 128-k weight buffers
#define SH    72     // halves stride, 64-k buffers (A0, W2, A2W)

// ---- smem byte offsets ----
#define O_A0   0u        // 128 x SH halves : e_uv -> e_r -> o
#define O_W1   18432u    // 64 x SA halves (k 0..63 = uv part, 64..127 = r part)
#define O_A1W  35840u    // 64 x SA halves (A1_top k 0..63, A1_bot k 64..127)
#define O_W2   53248u    // 64 x SH halves
#define O_A2W  62464u    // 64 x SH halves
#define O_B1   71680u
#define O_B2   71936u
#define O_AB1  72192u
#define O_AB2  72448u
#define O_A3   72704u
#define O_UVA  72960u    // 2 x 64 fp32 : uv @ A1_bot
#define O_LG   73472u    // 128 fp32 logits
#define SMEM_BYTES 73984u

__device__ __forceinline__ void mma16(float (&d)[4], uint32_t a0, uint32_t a1,
                                      uint32_t a2, uint32_t a3, uint32_t b0, uint32_t b1) {
    asm volatile(
        "mma.sync.aligned.m16n8k16.row.col.f32.f16.f16.f32 "
        "{%0,%1,%2,%3}, {%4,%5,%6,%7}, {%8,%9}, {%0,%1,%2,%3};"
        : "+f"(d[0]), "+f"(d[1]), "+f"(d[2]), "+f"(d[3])
        : "r"(a0), "r"(a1), "r"(a2), "r"(a3), "r"(b0), "r"(b1));
}

__device__ __forceinline__ uint32_t h2(float lo, float hi) {
    __half2 h = __floats2half2_rn(lo, hi);
    return *reinterpret_cast<uint32_t*>(&h);
}

// fp16 storage index of logical col c within a row (pair-permuted k16 groups)
__device__ __forceinline__ int offcol(int c) {
    int gg = c >> 4, kr = c & 15, p = kr >> 1;
    int slot = (p & 3) * 2 + (p >> 2);
    return gg * 16 + slot * 2 + (kr & 1);
}

// smem-A GEMM (K=64): d[2 m16][8 n8] += A(rows 32*wq..+31) @ B(all 64 n)^T
template <int SAs, int SBs>
__device__ __forceinline__ void gemm_fw(const __half* __restrict__ As,
                                        const __half* __restrict__ Bs,
                                        float (&d)[2][8][4],
                                        int wq, int r, int m) {
    const __half* pa = As + (wq * 32 + r) * SAs + m * 4;
    const __half* pb = Bs + r * SBs + m * 4;
#pragma unroll
    for (int g = 0; g < 4; g++) {
        uint2 aA = *(const uint2*)(pa + 16 * g);
        uint2 aB = *(const uint2*)(pa + 8 * SAs + 16 * g);
        uint2 aC = *(const uint2*)(pa + 16 * SAs + 16 * g);
        uint2 aD = *(const uint2*)(pa + 24 * SAs + 16 * g);
        uint2 bv[8];
#pragma unroll
        for (int nt = 0; nt < 8; nt++)
            bv[nt] = *(const uint2*)(pb + nt * 8 * SBs + 16 * g);
#pragma unroll
        for (int nt = 0; nt < 8; nt++) {
            mma16(d[0][nt], aA.x, aB.x, aA.y, aB.y, bv[nt].x, bv[nt].y);
            mma16(d[1][nt], aC.x, aD.x, aC.y, aD.y, bv[nt].x, bv[nt].y);
        }
    }
}

// register-A GEMM (K=64): a[mt][kg][0..3] are A-fragments, B from smem.
template <int SBs>
__device__ __forceinline__ void gemm_regA(const __half* __restrict__ Bs,
                                          const uint32_t (&a)[2][4][4],
                                          float (&d)[2][8][4], int r, int m) {
    const __half* pb = Bs + r * SBs + m * 4;
#pragma unroll
    for (int kg = 0; kg < 4; kg++) {
        uint2 bv[8];
#pragma unroll
        for (int nt = 0; nt < 8; nt++)
            bv[nt] = *(const uint2*)(pb + nt * 8 * SBs + 16 * kg);
#pragma unroll
        for (int nt = 0; nt < 8; nt++) {
            mma16(d[0][nt], a[0][kg][0], a[0][kg][1], a[0][kg][2], a[0][kg][3],
                  bv[nt].x, bv[nt].y);
            mma16(d[1][nt], a[1][kg][0], a[1][kg][1], a[1][kg][2], a[1][kg][3],
                  bv[nt].x, bv[nt].y);
        }
    }
}

__device__ __forceinline__ void zero_acc(float (&d)[2][8][4]) {
#pragma unroll
    for (int i = 0; i < 2; i++)
#pragma unroll
        for (int j = 0; j < 8; j++)
#pragma unroll
            for (int k = 0; k < 4; k++) d[i][j][k] = 0.f;
}

// accum -> next-stage A-fragments: h[mt][kg] = relu(d + bias) packed half2.
__device__ __forceinline__ void cvt_stage(const float (&d)[2][8][4],
                                          const float* __restrict__ bias,
                                          uint32_t (&h)[2][4][4], int m) {
#pragma unroll
    for (int kg = 0; kg < 4; kg++) {
        int ca = kg * 16 + 2 * m, cb = ca + 8;
        float2 bA = *(const float2*)(bias + ca);
        float2 bB = *(const float2*)(bias + cb);
#pragma unroll
        for (int mt = 0; mt < 2; mt++) {
            h[mt][kg][0] = h2(fmaxf(d[mt][2*kg][0] + bA.x, 0.f),
                              fmaxf(d[mt][2*kg][1] + bA.y, 0.f));
            h[mt][kg][1] = h2(fmaxf(d[mt][2*kg][2] + bA.x, 0.f),
                              fmaxf(d[mt][2*kg][3] + bA.y, 0.f));
            h[mt][kg][2] = h2(fmaxf(d[mt][2*kg+1][0] + bB.x, 0.f),
                              fmaxf(d[mt][2*kg+1][1] + bB.y, 0.f));
            h[mt][kg][3] = h2(fmaxf(d[mt][2*kg+1][2] + bB.x, 0.f),
                              fmaxf(d[mt][2*kg+1][3] + bB.y, 0.f));
        }
    }
}

// stage-3 variant: + uvatt[node(row)]
__device__ __forceinline__ void cvt_stage3(const float (&d)[2][8][4],
                                           const float* __restrict__ bias,
                                           const float* __restrict__ uva,
                                           uint32_t (&h)[2][4][4],
                                           int wq, int r, int m) {
#pragma unroll
    for (int mt = 0; mt < 2; mt++) {
        int row0 = wq * 32 + mt * 16 + r;
        const float* ua = uva + ((row0 >= LHIST) ? 64 : 0);       // rows r
        const float* ub = uva + ((row0 + 8 >= LHIST) ? 64 : 0);   // rows r+8
#pragma unroll
        for (int kg = 0; kg < 4; kg++) {
            int ca = kg * 16 + 2 * m, cb = ca + 8;
            float2 bA = *(const float2*)(bias + ca);
            float2 bB = *(const float2*)(bias + cb);
            float2 uaA = *(const float2*)(ua + ca);
            float2 uaB = *(const float2*)(ua + cb);
            float2 ubA = *(const float2*)(ub + ca);
            float2 ubB = *(const float2*)(ub + cb);
            h[mt][kg][0] = h2(fmaxf(d[mt][2*kg][0] + bA.x + uaA.x, 0.f),
                              fmaxf(d[mt][2*kg][1] + bA.y + uaA.y, 0.f));
            h[mt][kg][1] = h2(fmaxf(d[mt][2*kg][2] + bA.x + ubA.x, 0.f),
                              fmaxf(d[mt][2*kg][3] + bA.y + ubA.y, 0.f));
            h[mt][kg][2] = h2(fmaxf(d[mt][2*kg+1][0] + bB.x + uaB.x, 0.f),
                              fmaxf(d[mt][2*kg+1][1] + bB.y + uaB.y, 0.f));
            h[mt][kg][3] = h2(fmaxf(d[mt][2*kg+1][2] + bB.x + ubB.x, 0.f),
                              fmaxf(d[mt][2*kg+1][3] + bB.y + ubB.y, 0.f));
        }
    }
}

// store o fragments to A0 (k-storage layout, stride SH)
__device__ __forceinline__ void store_o(const uint32_t (&h)[2][4][4],
                                        __half* __restrict__ dst,
                                        int wq, int r, int m) {
#pragma unroll
    for (int mt = 0; mt < 2; mt++) {
        int row0 = wq * 32 + mt * 16 + r;
#pragma unroll
        for (int kg = 0; kg < 4; kg++) {
            int hoff = kg * 16 + m * 4;
            *reinterpret_cast<uint2*>(dst + row0 * SH + hoff) =
                make_uint2(h[mt][kg][0], h[mt][kg][2]);
            *reinterpret_cast<uint2*>(dst + (row0 + 8) * SH + hoff) =
                make_uint2(h[mt][kg][1], h[mt][kg][3]);
        }
    }
}

// stage weight W[K][64] (gmem row-major) -> half dst[n][k-storage].
__device__ __forceinline__ void stage_wh(__half* __restrict__ dst, const float* __restrict__ W,
                                         int K, int strh, int tid) {
    for (int idx = tid; idx < K * 64; idx += TPB) {
        int k = idx >> 6, n = idx & 63;
        dst[n * strh + offcol(k)] = __float2half_rn(W[idx]);
    }
}

// gather one 64-float embedding row into A0 k-storage (8x STS.128)
__device__ __forceinline__ void gather_row(__half* __restrict__ drowp,
                                           const float* __restrict__ src) {
    uint4* drow = reinterpret_cast<uint4*>(drowp);
#pragma unroll
    for (int gg = 0; gg < 4; gg++) {
        float4 f0 = *(const float4*)(src + gg * 16 + 0);
        float4 f1 = *(const float4*)(src + gg * 16 + 4);
        float4 f2 = *(const float4*)(src + gg * 16 + 8);
        float4 f3 = *(const float4*)(src + gg * 16 + 12);
        uint4 lo, hi;
        lo.x = h2(f0.x, f0.y);  lo.y = h2(f2.x, f2.y);
        lo.z = h2(f0.z, f0.w);  lo.w = h2(f2.z, f2.w);
        hi.x = h2(f1.x, f1.y);  hi.y = h2(f3.x, f3.y);
        hi.z = h2(f1.z, f1.w);  hi.w = h2(f3.z, f3.w);
        drow[gg * 2] = lo; drow[gg * 2 + 1] = hi;
    }
}

__global__ __launch_bounds__(TPB, 3)
void uv_agg_r3(const int* __restrict__ nodes,
               const int* __restrict__ hist_uv,
               const int* __restrict__ hist_r,
               const float* __restrict__ v2e,
               const float* __restrict__ u2e,
               const float* __restrict__ r2e,
               const float* __restrict__ w1, const float* __restrict__ b1,
               const float* __restrict__ w2, const float* __restrict__ b2,
               const float* __restrict__ a1w, const float* __restrict__ a1b,
               const float* __restrict__ a2w, const float* __restrict__ a2b,
               const float* __restrict__ a3w, const float* __restrict__ a3b,
               float* __restrict__ out, int ngroups) {
    extern __shared__ char smem[];
    __half* hA0  = reinterpret_cast<__half*>(smem + O_A0);
    __half* hW1  = reinterpret_cast<__half*>(smem + O_W1);
    __half* hA1W = reinterpret_cast<__half*>(smem + O_A1W);
    __half* hW2  = reinterpret_cast<__half*>(smem + O_W2);
    __half* hA2W = reinterpret_cast<__half*>(smem + O_A2W);
    float* fB1  = reinterpret_cast<float*>(smem + O_B1);
    float* fB2  = reinterpret_cast<float*>(smem + O_B2);
    float* fAB1 = reinterpret_cast<float*>(smem + O_AB1);
    float* fAB2 = reinterpret_cast<float*>(smem + O_AB2);
    float* fA3  = reinterpret_cast<float*>(smem + O_A3);
    float* fUVA = reinterpret_cast<float*>(smem + O_UVA);
    float* fLG  = reinterpret_cast<float*>(smem + O_LG);

    const int tid = threadIdx.x;
    const int wid = tid >> 5, lane = tid & 31;
    const int r = lane >> 2, m = lane & 3;

    // ---- stage weights + biases once per CTA ----
    stage_wh(hW1, w1, 128, SA, tid);
    stage_wh(hA1W, a1w, 128, SA, tid);   // k 0..63 = A1_top, k 64..127 = A1_bot
    stage_wh(hW2, w2, 64, SH, tid);
    stage_wh(hA2W, a2w, 64, SH, tid);
    if (tid < 64) {
        fB1[tid]  = b1[tid];
        fB2[tid]  = b2[tid];
        fAB1[tid] = a1b[tid];
        fAB2[tid] = a2b[tid];
        fA3[tid]  = a3w[tid];
    }
    __syncthreads();

    const int sn = tid >> 6;       // softmax: node
    const int sd = tid & 63;       // softmax: dim
    const int sdo = offcol(sd);

    const int grow = wid * 32 + lane;
    const bool gvalid = grow < VROWS;
    const int gn = (grow >= LHIST) ? 1 : 0;
    const int gl = grow - gn * LHIST;

    for (int g = blockIdx.x; g < ngroups; g += gridDim.x) {
        const int b0 = g * NB;
        int hidx = (b0 + gn) * LHIST + gl;
        int iu = 0, ir = 0;
        if (gvalid) { iu = hist_uv[hidx]; ir = hist_r[hidx]; }

        // ---- uvatt: warps 0,1 compute uv[n] . A1_bot (uv read from gmem) ----
        if (wid < 2) {
            const float* uvg = u2e + (size_t)nodes[b0 + wid] * 64;
#pragma unroll
            for (int cc = 0; cc < 2; cc++) {
                int c = lane + cc * 32;
                const uint4* w4 = reinterpret_cast<const uint4*>(hA1W + c * SA + 64);
                float acc = 0.f;
#pragma unroll
                for (int gg = 0; gg < 4; gg++) {
                    const float* u = uvg + gg * 16;
                    float4 u0 = *(const float4*)(u + 0);
                    float4 u1 = *(const float4*)(u + 4);
                    float4 u2v = *(const float4*)(u + 8);
                    float4 u3 = *(const float4*)(u + 12);
                    uint4 wa = w4[gg * 2], wb = w4[gg * 2 + 1];
                    float2 q;
                    q = __half22float2(*reinterpret_cast<__half2*>(&wa.x)); acc += q.x*u0.x + q.y*u0.y;
                    q = __half22float2(*reinterpret_cast<__half2*>(&wa.y)); acc += q.x*u2v.x + q.y*u2v.y;
                    q = __half22float2(*reinterpret_cast<__half2*>(&wa.z)); acc += q.x*u0.z + q.y*u0.w;
                    q = __half22float2(*reinterpret_cast<__half2*>(&wa.w)); acc += q.x*u2v.z + q.y*u2v.w;
                    q = __half22float2(*reinterpret_cast<__half2*>(&wb.x)); acc += q.x*u1.x + q.y*u1.y;
                    q = __half22float2(*reinterpret_cast<__half2*>(&wb.y)); acc += q.x*u3.x + q.y*u3.y;
                    q = __half22float2(*reinterpret_cast<__half2*>(&wb.z)); acc += q.x*u1.z + q.y*u1.w;
                    q = __half22float2(*reinterpret_cast<__half2*>(&wb.w)); acc += q.x*u3.z + q.y*u3.w;
                }
                fUVA[wid * 64 + c] = acc;
            }
        }

        float d[2][8][4];
        uint32_t h[2][4][4];

        // ==== GEMM1a: e_uv @ W1[k 0..63] ====
        if (gvalid) gather_row(hA0 + grow * SH, v2e + (size_t)iu * 64);
        __syncwarp();
        zero_acc(d);
        gemm_fw<SH, SA>(hA0, hW1, d, wid, r, m);
        __syncwarp();

        // ==== GEMM1b: += e_r @ W1[k 64..127] ====
        if (gvalid) gather_row(hA0 + grow * SH, r2e + (size_t)ir * 64);
        __syncwarp();
        gemm_fw<SH, SA>(hA0, hW1 + 64, d, wid, r, m);
        cvt_stage(d, fB1, h, m);

        // ==== GEMM2: o = relu(H @ W2 + b2) — A from regs ====
        zero_acc(d);
        gemm_regA<SH>(hW2, h, d, r, m);
        cvt_stage(d, fB2, h, m);
        __syncwarp();                      // A0 (e_r) reads done before o store
        store_o(h, hA0, wid, r, m);        // warp-private rows

        // ==== GEMM3: H2 = relu(o @ A1_top + ab1 + uvatt[n]) — A from regs ====
        // uvatt produced by warps 0,1 this iteration; consumed via cvt_stage3.
        zero_acc(d);
        gemm_regA<SA>(hA1W, h, d, r, m);
        __syncthreads();                   // S1: uvatt visible to all warps
        cvt_stage3(d, fAB1, fUVA, h, wid, r, m);

        // ==== GEMM4 + full logit dot ====
        zero_acc(d);
        gemm_regA<SH>(hA2W, h, d, r, m);
        {
            float p0[2] = {0.f, 0.f}, p1[2] = {0.f, 0.f};
#pragma unroll
            for (int mt = 0; mt < 2; mt++)
#pragma unroll
                for (int nt = 0; nt < 8; nt++) {
                    int c0 = nt * 8 + 2 * m;
                    float w30 = fA3[c0], w31 = fA3[c0 + 1];
                    float bb0 = fAB2[c0], bb1 = fAB2[c0 + 1];
                    p0[mt] += fmaxf(d[mt][nt][0] + bb0, 0.f) * w30
                            + fmaxf(d[mt][nt][1] + bb1, 0.f) * w31;
                    p1[mt] += fmaxf(d[mt][nt][2] + bb0, 0.f) * w30
                            + fmaxf(d[mt][nt][3] + bb1, 0.f) * w31;
                }
#pragma unroll
            for (int off = 1; off <= 2; off <<= 1) {
#pragma unroll
                for (int mt = 0; mt < 2; mt++) {
                    p0[mt] += __shfl_xor_sync(0xffffffffu, p0[mt], off);
                    p1[mt] += __shfl_xor_sync(0xffffffffu, p1[mt], off);
                }
            }
            if (m == 0) {
#pragma unroll
                for (int mt = 0; mt < 2; mt++) {
                    int row = wid * 32 + mt * 16 + r;
                    fLG[row] = p0[mt];
                    fLG[row + 8] = p1[mt];
                }
            }
        }
        __syncthreads();                               // S2: logits + o ready

        // ---- softmax(50) + weighted sum of o (fp16 from A0) ----
        {
            const float* lg = fLG + sn * LHIST;
            const __half* ob = hA0 + sn * LHIST * SH + sdo;
            float mx = -1e30f;
#pragma unroll 10
            for (int l = 0; l < LHIST; l++) mx = fmaxf(mx, lg[l]);
            float s = 0.f, acc = 0.f;
#pragma unroll 10
            for (int l = 0; l < LHIST; l++) {
                float e = __expf(lg[l] - mx);
                s += e;
                acc += e * __half2float(ob[l * SH]);
            }
            out[(size_t)(b0 + sn) * 64 + sd] = acc / s;
        }
        __syncthreads();                               // S3: A0/fLG/fUVA free
    }
}

extern "C" void kernel_launch(void* const* d_in, const int* in_sizes, int n_in,
                              void* d_out, int out_size) {
    const int*   nodes = (const int*)d_in[0];
    const int*   huv   = (const int*)d_in[1];
    const int*   hr    = (const int*)d_in[2];
    const float* v2e   = (const float*)d_in[3];
    const float* u2e   = (const float*)d_in[4];
    const float* r2e   = (const float*)d_in[5];
    const float* w1    = (const float*)d_in[6];
    const float* b1    = (const float*)d_in[7];
    const float* w2    = (const float*)d_in[8];
    const float* b2    = (const float*)d_in[9];
    const float* a1w   = (const float*)d_in[10];
    const float* a1b   = (const float*)d_in[11];
    const float* a2w   = (const float*)d_in[12];
    const float* a2b   = (const float*)d_in[13];
    const float* a3w   = (const float*)d_in[14];
    const float* a3b   = (const float*)d_in[15];
    float* out = (float*)d_out;

    const int B = in_sizes[0];
    const int ngroups = B / NB;

    static int attr_set = 0;
    if (!attr_set) {
        cudaFuncSetAttribute(uv_agg_r3, cudaFuncAttributeMaxDynamicSharedMemorySize, SMEM_BYTES);
        attr_set = 1;
    }
    uv_agg_r3<<<444, TPB, SMEM_BYTES>>>(nodes, huv, hr, v2e, u2e, r2e,
                                        w1, b1, w2, b2, a1w, a1b, a2w, a2b,
                                        a3w, a3b, out, ngroups);
}